// round 9
// baseline (speedup 1.0000x reference)
#include <cuda_runtime.h>
#include <cstdint>

#define BATCH 64
#define SEQ   64
#define D     256
#define HALF  128
#define NCOL  640      // 5 * HALF
#define MLPD  1024
#define KC    16       // k-chunk rows staged per step
#define NCHUNK (D / KC)  // 16
#define NTHREADS 512
#define NWARPS 16

// ---------------- smem layout (floats) ----------------
static constexpr int SA_OFF    = 0;                         // 65*256
static constexpr int SB_OFF    = SA_OFF + 65 * D;           // 65*256
static constexpr int SW_OFF    = SB_OFF + 65 * D;           // 2*16*640
static constexpr int SBIAS_OFF = SW_OFF + 2 * KC * NCOL;    // 640
static constexpr int SSELW_OFF = SBIAS_OFF + NCOL;          // 256
static constexpr int SLOG_OFF  = SSELW_OFF + D;             // 64
static constexpr int SPROB_OFF = SLOG_OFF + 64;             // 64
static constexpr int SCL_OFF   = SPROB_OFF + 64;            // 64
static constexpr int SCR_OFF   = SCL_OFF + 64;              // 64
static constexpr int SMEM_FLOATS = SCR_OFF + 64;
static constexpr int SMEM_BYTES  = SMEM_FLOATS * 4;         // 219,648 B

// ---------------- helpers ----------------
__device__ __forceinline__ unsigned smaddr(const void* p) {
    return (unsigned)__cvta_generic_to_shared(p);
}
__device__ __forceinline__ void cp16(unsigned dst, const void* src) {
    asm volatile("cp.async.ca.shared.global [%0], [%1], 16;\n" :: "r"(dst), "l"(src));
}
__device__ __forceinline__ void cp_commit() {
    asm volatile("cp.async.commit_group;\n" ::: "memory");
}
__device__ __forceinline__ void fma2(unsigned long long& a, unsigned long long b, unsigned long long c) {
    asm("fma.rn.f32x2 %0, %1, %2, %0;" : "+l"(a) : "l"(b), "l"(c));
}
__device__ __forceinline__ unsigned long long splat(float x) {
    unsigned long long r;
    unsigned u = __float_as_uint(x);
    asm("mov.b64 %0, {%1, %1};" : "=l"(r) : "r"(u));
    return r;
}
__device__ __forceinline__ float2 unpack2(unsigned long long v) {
    float2 f;
    asm("mov.b64 {%0, %1}, %2;" : "=f"(f.x), "=f"(f.y) : "l"(v));
    return f;
}
__device__ __forceinline__ float sigm(float x) {
    return __fdividef(1.f, 1.f + __expf(-x));
}
__device__ __forceinline__ float tanh_f(float x) {
    // stable: 1 - 2/(e^{2x}+1); saturates correctly at +/-1
    return 1.f - 2.f * __fdividef(1.f, __expf(2.f * x) + 1.f);
}
__device__ __forceinline__ float incl_scan(float v, int lane) {
    #pragma unroll
    for (int d = 1; d < 32; d <<= 1) {
        float n = __shfl_up_sync(0xffffffffu, v, d);
        if (lane >= d) v += n;
    }
    return v;
}

// ---------------- kernel ----------------
__global__ __launch_bounds__(NTHREADS, 1)
void pyramid_kernel(const int* __restrict__ sentences,   // int32 tokens (or int64; probed)
                    const float* __restrict__ emb,
                    const float* __restrict__ comp_W,
                    const float* __restrict__ comp_b,
                    const float* __restrict__ sel_w,
                    const float* __restrict__ sel_b,
                    const float* __restrict__ w0, const float* __restrict__ b0,
                    const float* __restrict__ w1, const float* __restrict__ b1,
                    const float* __restrict__ cw, const float* __restrict__ cb,
                    float* __restrict__ out)
{
    extern __shared__ float sm[];
    float* sBufA = sm + SA_OFF;
    float* sBufB = sm + SB_OFF;
    float* sW    = sm + SW_OFF;
    float* sbias = sm + SBIAS_OFF;
    float* sselw = sm + SSELW_OFF;
    float* slog  = sm + SLOG_OFF;
    float* sprob = sm + SPROB_OFF;
    float* scl   = sm + SCL_OFF;
    float* scr   = sm + SCR_OFF;

    const int tid  = threadIdx.x;
    const int lane = tid & 31;
    const int wid  = tid >> 5;
    const int b    = blockIdx.x;

    // dtype probe: JAX default (x64 disabled) gives int32 tokens. If the data
    // really were int64 (little-endian, values < VOCAB), every odd 32-bit word
    // of the first tokens would be zero. Random tokens in [0,32000) make a
    // false positive on int32 data astronomically unlikely (~(1/32000)^4).
    const bool is64 = (sentences[1] == 0 && sentences[3] == 0 &&
                       sentences[5] == 0 && sentences[7] == 0);

    // ---- init: gather embeddings into sBufA ----
    {
        float4* a4 = (float4*)sBufA;
        const float4* e4 = (const float4*)emb;
        for (int i = tid; i < SEQ * (D / 4); i += NTHREADS) {
            int row = i >> 6;          // D/4 = 64
            int c4  = i & 63;
            int idx = b * SEQ + row;
            int tok = is64 ? sentences[idx * 2] : sentences[idx];
            a4[row * 64 + c4] = e4[tok * 64 + c4];
        }
        float4 z4 = make_float4(0.f, 0.f, 0.f, 0.f);
        for (int i = tid; i < 64; i += NTHREADS) a4[64 * 64 + i] = z4;  // zero pad row 64
        for (int i = tid; i < NCOL; i += NTHREADS) sbias[i] = comp_b[i];
        for (int i = tid; i < D;    i += NTHREADS) sselw[i] = sel_w[i];
    }
    const float selb = sel_b[0];
    __syncthreads();

    float* sCur = sBufA;
    float* sNxt = sBufB;

    const int pb = wid >> 1;             // position block 0..7 (8 positions each)
    const int mb = wid & 1;              // m-half block
    const int m0 = mb * 64 + 2 * lane;   // hidden-index pair base (even)

    for (int P = SEQ - 1; P >= 1; --P) {
        const int  pbase  = pb * 8;
        const bool active = (pbase < P);

        // ================= GEMM: a = [hl|hr] @ comp_W =================
        unsigned long long acc[5][8];
        if (active) {
            #pragma unroll
            for (int g = 0; g < 5; ++g)
                #pragma unroll
                for (int t = 0; t < 8; ++t) acc[g][t] = 0ull;
        }

        // prologue: stage chunk 0
        {
            unsigned dstb = smaddr(sW);
            const float* src = comp_W;
            #pragma unroll
            for (int i = tid; i < KC * NCOL / 4; i += NTHREADS)
                cp16(dstb + (unsigned)i * 16u, src + i * 4);
            cp_commit();
        }

        for (int c = 0; c < NCHUNK; ++c) {
            if (c + 1 < NCHUNK) {
                unsigned dstb = smaddr(sW + ((c + 1) & 1) * KC * NCOL);
                const float* src = comp_W + (c + 1) * KC * NCOL;
                #pragma unroll
                for (int i = tid; i < KC * NCOL / 4; i += NTHREADS)
                    cp16(dstb + (unsigned)i * 16u, src + i * 4);
                cp_commit();
                asm volatile("cp.async.wait_group 1;\n" ::: "memory");
            } else {
                asm volatile("cp.async.wait_group 0;\n" ::: "memory");
            }
            __syncthreads();   // chunk c visible to all

            if (active) {
                const int k0 = c * KC;
                // k < 128 -> h of states[p]; k >= 128 -> h of states[p+1]
                const float* xbase = sCur + (pbase + (k0 >= HALF ? 1 : 0)) * D + (k0 & (HALF - 1));
                const float* wb    = sW + (c & 1) * KC * NCOL + m0;
                #pragma unroll
                for (int kk = 0; kk < KC; ++kk) {
                    unsigned long long w[5];
                    #pragma unroll
                    for (int g = 0; g < 5; ++g)
                        w[g] = *(const unsigned long long*)(wb + kk * NCOL + g * HALF);
                    #pragma unroll
                    for (int t = 0; t < 8; ++t) {
                        unsigned long long xs = splat(xbase[t * D + kk]);
                        #pragma unroll
                        for (int g = 0; g < 5; ++g) fma2(acc[g][t], w[g], xs);
                    }
                }
            }
            __syncthreads();   // before overwriting the other W buffer
        }

        // ================= gates epilogue (in registers) =================
        if (active) {
            const float bi0 = sbias[0 * HALF + m0], bi1 = sbias[0 * HALF + m0 + 1];
            const float bl0 = sbias[1 * HALF + m0], bl1 = sbias[1 * HALF + m0 + 1];
            const float br0 = sbias[2 * HALF + m0], br1 = sbias[2 * HALF + m0 + 1];
            const float bg0 = sbias[3 * HALF + m0], bg1 = sbias[3 * HALF + m0 + 1];
            const float bo0 = sbias[4 * HALF + m0], bo1 = sbias[4 * HALF + m0 + 1];
            #pragma unroll
            for (int t = 0; t < 8; ++t) {
                const int p = pbase + t;
                float2 iv = unpack2(acc[0][t]);
                float2 fl = unpack2(acc[1][t]);
                float2 fr = unpack2(acc[2][t]);
                float2 gg = unpack2(acc[3][t]);
                float2 oo = unpack2(acc[4][t]);
                float2 cl = *(const float2*)(sCur + p * D + HALF + m0);
                float2 cr = *(const float2*)(sCur + (p + 1) * D + HALF + m0);

                float cx = sigm(fl.x + bl0) * cl.x + sigm(fr.x + br0) * cr.x
                         + sigm(iv.x + bi0) * tanh_f(gg.x + bg0);
                float cy = sigm(fl.y + bl1) * cl.y + sigm(fr.y + br1) * cr.y
                         + sigm(iv.y + bi1) * tanh_f(gg.y + bg1);
                float hx = sigm(oo.x + bo0) * tanh_f(cx);
                float hy = sigm(oo.y + bo1) * tanh_f(cy);

                *(float2*)(sNxt + p * D + m0)        = make_float2(hx, hy);
                *(float2*)(sNxt + p * D + HALF + m0) = make_float2(cx, cy);
            }
        }
        __syncthreads();

        // ================= logits: comp @ sel_w =================
        for (int p = wid; p < P; p += NWARPS) {
            const float* cp = sNxt + p * D;
            float s = 0.f;
            #pragma unroll
            for (int r = 0; r < 2; ++r) {
                float4 v = *(const float4*)(cp + lane * 8 + r * 4);
                float4 w = *(const float4*)(sselw + lane * 8 + r * 4);
                s += v.x * w.x + v.y * w.y + v.z * w.z + v.w * w.w;
            }
            #pragma unroll
            for (int d2 = 16; d2; d2 >>= 1) s += __shfl_xor_sync(0xffffffffu, s, d2);
            if (lane == 0) slog[p] = s + selb;
        }
        __syncthreads();

        // ================= softmax + exclusive scans (warp 0) =================
        if (wid == 0) {
            float v0 = (lane      < P) ? slog[lane]      : -3.4e38f;
            float v1 = (lane + 32 < P) ? slog[lane + 32] : -3.4e38f;
            float mx = fmaxf(v0, v1);
            #pragma unroll
            for (int d2 = 16; d2; d2 >>= 1) mx = fmaxf(mx, __shfl_xor_sync(0xffffffffu, mx, d2));
            float e0 = (lane      < P) ? __expf(v0 - mx) : 0.f;
            float e1 = (lane + 32 < P) ? __expf(v1 - mx) : 0.f;
            float ss = e0 + e1;
            #pragma unroll
            for (int d2 = 16; d2; d2 >>= 1) ss += __shfl_xor_sync(0xffffffffu, ss, d2);
            float inv = __fdividef(1.f, ss);
            float p0 = e0 * inv, p1 = e1 * inv;
            float s0 = incl_scan(p0, lane);
            float t0 = __shfl_sync(0xffffffffu, s0, 31);
            float s1 = incl_scan(p1, lane) + t0;
            float tt = __shfl_sync(0xffffffffu, s1, 31);
            if (lane < P)      { sprob[lane]      = p0; scr[lane]      = s0 - p0; scl[lane]      = tt - s0; }
            if (lane + 32 < P) { sprob[lane + 32] = p1; scr[lane + 32] = s1 - p1; scl[lane + 32] = tt - s1; }
        }
        __syncthreads();

        // ================= state update (into comp buffer) =================
        {
            float4*       nx4 = (float4*)sNxt;
            const float4* cu4 = (const float4*)sCur;
            for (int i = tid; i < P * 64; i += NTHREADS) {
                int   p  = i >> 6;
                float a  = scl[p], r = scr[p], q = sprob[p];
                float4 L = cu4[i];
                float4 R = cu4[i + 64];
                float4 C = nx4[i];
                float4 o;
                o.x = a * L.x + r * R.x + q * C.x;
                o.y = a * L.y + r * R.y + q * C.y;
                o.z = a * L.z + r * R.z + q * C.z;
                o.w = a * L.w + r * R.w + q * C.w;
                nx4[i] = o;
            }
            // zero pad rows [P, min(P+8,64)] so padded GEMM reads are harmless
            int z1 = min(P + 9, 65) * 64;
            float4 z4 = make_float4(0.f, 0.f, 0.f, 0.f);
            for (int i = P * 64 + tid; i < z1; i += NTHREADS) nx4[i] = z4;
        }
        __syncthreads();

        float* t2 = sCur; sCur = sNxt; sNxt = t2;
    }

    // ================= MLP head: row 0 of sCur =================
    const float* h  = sCur;          // 256
    float*       z1 = sW;            // 1024
    float*       z2 = sW + MLPD;     // 1024
    {
        const int c0 = tid * 2;
        unsigned long long a2 = 0ull;
        for (int k = 0; k < D; ++k) {
            unsigned long long w2 = *(const unsigned long long*)(w0 + k * MLPD + c0);
            fma2(a2, w2, splat(h[k]));
        }
        float2 a = unpack2(a2);
        z1[c0]     = fmaxf(a.x + b0[c0],     0.f);
        z1[c0 + 1] = fmaxf(a.y + b0[c0 + 1], 0.f);
    }
    __syncthreads();
    {
        const int c0 = tid * 2;
        unsigned long long a2 = 0ull;
        for (int k = 0; k < MLPD; ++k) {
            unsigned long long w2 = *(const unsigned long long*)(w1 + k * MLPD + c0);
            fma2(a2, w2, splat(z1[k]));
        }
        float2 a = unpack2(a2);
        z2[c0]     = fmaxf(a.x + b1[c0],     0.f);
        z2[c0 + 1] = fmaxf(a.y + b1[c0 + 1], 0.f);
    }
    __syncthreads();
    if (wid == 0) {
        #pragma unroll
        for (int c = 0; c < 3; ++c) {
            float s = 0.f;
            for (int k = lane; k < MLPD; k += 32) s += z2[k] * cw[k * 3 + c];
            #pragma unroll
            for (int d2 = 16; d2; d2 >>= 1) s += __shfl_xor_sync(0xffffffffu, s, d2);
            if (lane == 0) out[b * 3 + c] = s + cb[c];
        }
    }
}

// ---------------- launch ----------------
extern "C" void kernel_launch(void* const* d_in, const int* in_sizes, int n_in,
                              void* d_out, int out_size)
{
    (void)in_sizes; (void)n_in; (void)out_size;
    const int* sentences = (const int*)d_in[0];
    // d_in[1] = transitions (unused)
    const float* emb    = (const float*)d_in[2];
    const float* comp_W = (const float*)d_in[3];
    const float* comp_b = (const float*)d_in[4];
    const float* sel_w  = (const float*)d_in[5];
    const float* sel_b  = (const float*)d_in[6];
    const float* w0     = (const float*)d_in[7];
    const float* b0     = (const float*)d_in[8];
    const float* w1     = (const float*)d_in[9];
    const float* b1     = (const float*)d_in[10];
    const float* cw     = (const float*)d_in[11];
    const float* cb     = (const float*)d_in[12];
    float* out = (float*)d_out;

    cudaFuncSetAttribute(pyramid_kernel,
                         cudaFuncAttributeMaxDynamicSharedMemorySize, SMEM_BYTES);
    pyramid_kernel<<<BATCH, NTHREADS, SMEM_BYTES>>>(
        sentences, emb, comp_W, comp_b, sel_w, sel_b,
        w0, b0, w1, b1, cw, cb, out);
}

// round 10
// speedup vs baseline: 1.9580x; 1.9580x over previous
#include <cuda_runtime.h>
#include <cstdint>

#define BATCH 64
#define SEQ   64
#define D     256
#define HALF  128
#define NCOL  640      // 5 * HALF (full gate width)
#define WCOL  320      // per-CTA gate columns (5 gates x 64)
#define MLPD  1024
#define KC    16       // k rows staged per chunk
#define NCHUNK (D / KC)  // 16
#define NTHREADS 512
#define NWARPS 16

typedef unsigned long long ull;

// ---------------- smem layout (floats) ----------------
static constexpr int SA_OFF    = 0;                          // 65*256 state buf A
static constexpr int SB_OFF    = SA_OFF + 65 * D;            // 65*256 state buf B
static constexpr int SW_OFF    = SB_OFF + 65 * D;            // 3*16*320 W ring
static constexpr int SBIAS_OFF = SW_OFF + 3 * KC * WCOL;     // 640
static constexpr int SSELW_OFF = SBIAS_OFF + NCOL;           // 256
static constexpr int SLOG_OFF  = SSELW_OFF + D;              // 64
static constexpr int SPROB_OFF = SLOG_OFF + 64;              // 64
static constexpr int SCL_OFF   = SPROB_OFF + 64;             // 64
static constexpr int SCR_OFF   = SCL_OFF + 64;               // 64
static constexpr int SMEM_FLOATS = SCR_OFF + 64;             // 49,792
static constexpr int SMEM_BYTES  = SMEM_FLOATS * 4;          // 199,168 B

// ---------------- helpers ----------------
__device__ __forceinline__ unsigned smaddr(const void* p) {
    return (unsigned)__cvta_generic_to_shared(p);
}
__device__ __forceinline__ void cp16(unsigned dst, const void* src) {
    asm volatile("cp.async.ca.shared.global [%0], [%1], 16;\n" :: "r"(dst), "l"(src));
}
__device__ __forceinline__ void cp_commit() {
    asm volatile("cp.async.commit_group;\n" ::: "memory");
}
__device__ __forceinline__ void fma2(ull& a, ull b, ull c) {
    asm("fma.rn.f32x2 %0, %1, %2, %0;" : "+l"(a) : "l"(b), "l"(c));
}
__device__ __forceinline__ ull splat(float x) {
    ull r; unsigned u = __float_as_uint(x);
    asm("mov.b64 %0, {%1, %1};" : "=l"(r) : "r"(u));
    return r;
}
__device__ __forceinline__ float2 unpack2(ull v) {
    float2 f;
    asm("mov.b64 {%0, %1}, %2;" : "=f"(f.x), "=f"(f.y) : "l"(v));
    return f;
}
__device__ __forceinline__ float sigm(float x) {
    return __fdividef(1.f, 1.f + __expf(-x));
}
__device__ __forceinline__ float tanh_f(float x) {
    return 1.f - 2.f * __fdividef(1.f, __expf(2.f * x) + 1.f);
}
__device__ __forceinline__ float incl_scan(float v, int lane) {
    #pragma unroll
    for (int d = 1; d < 32; d <<= 1) {
        float n = __shfl_up_sync(0xffffffffu, v, d);
        if (lane >= d) v += n;
    }
    return v;
}
__device__ __forceinline__ unsigned ctarank() {
    unsigned r; asm("mov.u32 %0, %%cluster_ctarank;" : "=r"(r)); return r;
}
__device__ __forceinline__ void cluster_sync() {
    asm volatile("barrier.cluster.arrive.aligned;" ::: "memory");
    asm volatile("barrier.cluster.wait.aligned;" ::: "memory");
}
// write a packed float2 into the peer CTA's smem at the same offset
__device__ __forceinline__ void st_peer64(const float* p, unsigned peer, float hx, float hy) {
    unsigned la = smaddr(p), ra;
    asm("mapa.shared::cluster.u32 %0, %1, %2;" : "=r"(ra) : "r"(la), "r"(peer));
    ull pv; asm("mov.b64 %0, {%1, %2};" : "=l"(pv) : "f"(hx), "f"(hy));
    asm volatile("st.shared::cluster.b64 [%0], %1;" :: "r"(ra), "l"(pv) : "memory");
}

// ---------------- kernel ----------------
__global__ __launch_bounds__(NTHREADS, 1) __cluster_dims__(2, 1, 1)
void pyramid_kernel(const int* __restrict__ sentences,   // int32 tokens (int64 probed)
                    const float* __restrict__ emb,
                    const float* __restrict__ comp_W,
                    const float* __restrict__ comp_b,
                    const float* __restrict__ sel_w,
                    const float* __restrict__ sel_b,
                    const float* __restrict__ w0, const float* __restrict__ b0,
                    const float* __restrict__ w1, const float* __restrict__ b1,
                    const float* __restrict__ cw, const float* __restrict__ cb,
                    float* __restrict__ out)
{
    extern __shared__ float sm[];
    float* sBufA = sm + SA_OFF;
    float* sBufB = sm + SB_OFF;
    float* sW    = sm + SW_OFF;
    float* sbias = sm + SBIAS_OFF;
    float* sselw = sm + SSELW_OFF;
    float* slog  = sm + SLOG_OFF;
    float* sprob = sm + SPROB_OFF;
    float* scl   = sm + SCL_OFF;
    float* scr   = sm + SCR_OFF;

    const int tid  = threadIdx.x;
    const int lane = tid & 31;
    const int wid  = tid >> 5;
    const unsigned rank = ctarank();
    const unsigned peer = rank ^ 1u;
    const int b = blockIdx.x >> 1;      // cluster id = batch element

    // dtype probe (JAX x64-disabled gives int32; see R7 analysis)
    const bool is64 = (sentences[1] == 0 && sentences[3] == 0 &&
                       sentences[5] == 0 && sentences[7] == 0);

    // ---- init: gather embeddings into sBufA (replicated in both CTAs) ----
    {
        float4* a4 = (float4*)sBufA;
        const float4* e4 = (const float4*)emb;
        for (int i = tid; i < SEQ * (D / 4); i += NTHREADS) {
            int row = i >> 6;
            int c4  = i & 63;
            int idx = b * SEQ + row;
            int tok = is64 ? sentences[idx * 2] : sentences[idx];
            a4[row * 64 + c4] = e4[tok * 64 + c4];
        }
        float4 z4 = make_float4(0.f, 0.f, 0.f, 0.f);
        for (int i = tid; i < 64; i += NTHREADS) a4[64 * 64 + i] = z4;  // pad row 64
        for (int i = tid; i < NCOL; i += NTHREADS) sbias[i] = comp_b[i];
        for (int i = tid; i < D;    i += NTHREADS) sselw[i] = sel_w[i];
    }
    const float selb = sel_b[0];
    __syncthreads();

    float* sCur = sBufA;
    float* sNxt = sBufB;

    const int pb    = wid;              // position block 0..15 (4 positions each)
    const int pbase = pb * 4;
    const int m0g   = (int)rank * 64 + 2 * lane;   // global hidden pair base

    // per-gate biases are loop-invariant: hoist
    float bia[5][2];
    #pragma unroll
    for (int g = 0; g < 5; ++g) {
        bia[g][0] = sbias[g * HALF + m0g];
        bia[g][1] = sbias[g * HALF + m0g + 1];
    }

    for (int P = SEQ - 1; P >= 1; --P) {
        const bool active = (pbase < P);

        // ================= GEMM: this CTA's 320 gate columns =================
        ull acc[5][4];
        if (active) {
            #pragma unroll
            for (int g = 0; g < 5; ++g)
                #pragma unroll
                for (int t = 0; t < 4; ++t) acc[g][t] = 0ull;
        }

        // stage chunk c into ring buffer c%3 (only our 320 columns)
        auto stage = [&](int c) {
            unsigned dstb = smaddr(sW + (c % 3) * KC * WCOL);
            const float* src = comp_W + c * KC * NCOL + rank * 64;
            #pragma unroll
            for (int i = tid; i < KC * WCOL / 4; i += NTHREADS) {   // 1280
                int kk  = i / 80;
                int rem = i - kk * 80;
                int g   = rem >> 4;
                int q   = rem & 15;
                cp16(dstb + (unsigned)((kk * WCOL + g * 64 + q * 4) * 4),
                     src + kk * NCOL + g * HALF + q * 4);
            }
            cp_commit();
        };

        stage(0);
        stage(1);

        for (int c = 0; c < NCHUNK; ++c) {
            if (c == NCHUNK - 1)
                asm volatile("cp.async.wait_group 0;\n" ::: "memory");
            else
                asm volatile("cp.async.wait_group 1;\n" ::: "memory");
            __syncthreads();                 // chunk c visible; chunk c-1 fully consumed
            if (c + 2 < NCHUNK) stage(c + 2);

            if (active) {
                const int k0 = c * KC;
                // k < 128 -> h of states[p]; k >= 128 -> h of states[p+1]
                const float* xb = sCur + (pbase + (k0 >= HALF ? 1 : 0)) * D + (k0 & (HALF - 1));
                const float* wb = sW + (c % 3) * KC * WCOL + 2 * lane;
                #pragma unroll
                for (int kk = 0; kk < KC; ++kk) {
                    ull w_[5];
                    #pragma unroll
                    for (int g = 0; g < 5; ++g)
                        w_[g] = *(const ull*)(wb + kk * WCOL + g * 64);
                    #pragma unroll
                    for (int t = 0; t < 4; ++t) {
                        ull xs = splat(xb[t * D + kk]);
                        #pragma unroll
                        for (int g = 0; g < 5; ++g) fma2(acc[g][t], w_[g], xs);
                    }
                }
            }
        }

        // ================= gates (registers) + local & peer writes =================
        if (active) {
            #pragma unroll
            for (int t = 0; t < 4; ++t) {
                const int p = pbase + t;
                float2 iv = unpack2(acc[0][t]);
                float2 fl = unpack2(acc[1][t]);
                float2 fr = unpack2(acc[2][t]);
                float2 gg = unpack2(acc[3][t]);
                float2 oo = unpack2(acc[4][t]);
                float2 cl = *(const float2*)(sCur + p * D + HALF + m0g);
                float2 cr = *(const float2*)(sCur + (p + 1) * D + HALF + m0g);

                float cx = sigm(fl.x + bia[1][0]) * cl.x + sigm(fr.x + bia[2][0]) * cr.x
                         + sigm(iv.x + bia[0][0]) * tanh_f(gg.x + bia[3][0]);
                float cy = sigm(fl.y + bia[1][1]) * cl.y + sigm(fr.y + bia[2][1]) * cr.y
                         + sigm(iv.y + bia[0][1]) * tanh_f(gg.y + bia[3][1]);
                float hx = sigm(oo.x + bia[4][0]) * tanh_f(cx);
                float hy = sigm(oo.y + bia[4][1]) * tanh_f(cy);

                float* ph = sNxt + p * D + m0g;
                float* pc = sNxt + p * D + HALF + m0g;
                *(float2*)ph = make_float2(hx, hy);
                *(float2*)pc = make_float2(cx, cy);
                st_peer64(ph, peer, hx, hy);
                st_peer64(pc, peer, cx, cy);
            }
        }
        cluster_sync();   // peer's half of comp visible; also CTA-wide barrier

        // ================= logits: comp @ sel_w (duplicated, cheap) =================
        for (int p = wid; p < P; p += NWARPS) {
            const float* cp = sNxt + p * D;
            float s = 0.f;
            #pragma unroll
            for (int r = 0; r < 2; ++r) {
                float4 v = *(const float4*)(cp + lane * 8 + r * 4);
                float4 w = *(const float4*)(sselw + lane * 8 + r * 4);
                s += v.x * w.x + v.y * w.y + v.z * w.z + v.w * w.w;
            }
            #pragma unroll
            for (int d2 = 16; d2; d2 >>= 1) s += __shfl_xor_sync(0xffffffffu, s, d2);
            if (lane == 0) slog[p] = s + selb;
        }
        __syncthreads();

        // ================= softmax + exclusive scans (warp 0) =================
        if (wid == 0) {
            float v0 = (lane      < P) ? slog[lane]      : -3.4e38f;
            float v1 = (lane + 32 < P) ? slog[lane + 32] : -3.4e38f;
            float mx = fmaxf(v0, v1);
            #pragma unroll
            for (int d2 = 16; d2; d2 >>= 1) mx = fmaxf(mx, __shfl_xor_sync(0xffffffffu, mx, d2));
            float e0 = (lane      < P) ? __expf(v0 - mx) : 0.f;
            float e1 = (lane + 32 < P) ? __expf(v1 - mx) : 0.f;
            float ss = e0 + e1;
            #pragma unroll
            for (int d2 = 16; d2; d2 >>= 1) ss += __shfl_xor_sync(0xffffffffu, ss, d2);
            float inv = __fdividef(1.f, ss);
            float p0 = e0 * inv, p1 = e1 * inv;
            float s0 = incl_scan(p0, lane);
            float t0 = __shfl_sync(0xffffffffu, s0, 31);
            float s1 = incl_scan(p1, lane) + t0;
            float tt = __shfl_sync(0xffffffffu, s1, 31);
            if (lane < P)      { sprob[lane]      = p0; scr[lane]      = s0 - p0; scl[lane]      = tt - s0; }
            if (lane + 32 < P) { sprob[lane + 32] = p1; scr[lane + 32] = s1 - p1; scl[lane + 32] = tt - s1; }
        }
        __syncthreads();

        // ================= state update (in-place into comp buffer) =================
        {
            float4*       nx4 = (float4*)sNxt;
            const float4* cu4 = (const float4*)sCur;
            for (int i = tid; i < P * 64; i += NTHREADS) {
                int   p  = i >> 6;
                float a  = scl[p], r = scr[p], q = sprob[p];
                float4 L = cu4[i];
                float4 R = cu4[i + 64];
                float4 C = nx4[i];
                float4 o;
                o.x = a * L.x + r * R.x + q * C.x;
                o.y = a * L.y + r * R.y + q * C.y;
                o.z = a * L.z + r * R.z + q * C.z;
                o.w = a * L.w + r * R.w + q * C.w;
                nx4[i] = o;
            }
            // zero pad rows [P, min(P+6,65)) so padded GEMM/gate reads are harmless
            int z1 = min(P + 6, 65) * 64;
            float4 z4 = make_float4(0.f, 0.f, 0.f, 0.f);
            for (int i = P * 64 + tid; i < z1; i += NTHREADS) nx4[i] = z4;
        }
        cluster_sync();   // peer done with sCur before next layer's peer-writes hit it

        float* t2 = sCur; sCur = sNxt; sNxt = t2;
    }

    // ================= MLP head (rank 0 only): row 0 of sCur =================
    if (rank == 0) {
        const float* h  = sCur;          // 256
        float*       z1 = sW;            // 1024 scratch
        float*       z2 = sW + MLPD;     // 1024 scratch
        {
            const int c0 = tid * 2;
            ull a2 = 0ull;
            for (int k = 0; k < D; ++k) {
                ull w2 = *(const ull*)(w0 + k * MLPD + c0);
                fma2(a2, w2, splat(h[k]));
            }
            float2 a = unpack2(a2);
            z1[c0]     = fmaxf(a.x + b0[c0],     0.f);
            z1[c0 + 1] = fmaxf(a.y + b0[c0 + 1], 0.f);
        }
        __syncthreads();
        {
            const int c0 = tid * 2;
            ull a2 = 0ull;
            for (int k = 0; k < MLPD; ++k) {
                ull w2 = *(const ull*)(w1 + k * MLPD + c0);
                fma2(a2, w2, splat(z1[k]));
            }
            float2 a = unpack2(a2);
            z2[c0]     = fmaxf(a.x + b1[c0],     0.f);
            z2[c0 + 1] = fmaxf(a.y + b1[c0 + 1], 0.f);
        }
        __syncthreads();
        if (wid == 0) {
            #pragma unroll
            for (int c = 0; c < 3; ++c) {
                float s = 0.f;
                for (int k = lane; k < MLPD; k += 32) s += z2[k] * cw[k * 3 + c];
                #pragma unroll
                for (int d2 = 16; d2; d2 >>= 1) s += __shfl_xor_sync(0xffffffffu, s, d2);
                if (lane == 0) out[b * 3 + c] = s + cb[c];
            }
        }
    }
}

// ---------------- launch ----------------
extern "C" void kernel_launch(void* const* d_in, const int* in_sizes, int n_in,
                              void* d_out, int out_size)
{
    (void)in_sizes; (void)n_in; (void)out_size;
    const int* sentences = (const int*)d_in[0];
    // d_in[1] = transitions (unused)
    const float* emb    = (const float*)d_in[2];
    const float* comp_W = (const float*)d_in[3];
    const float* comp_b = (const float*)d_in[4];
    const float* sel_w  = (const float*)d_in[5];
    const float* sel_b  = (const float*)d_in[6];
    const float* w0     = (const float*)d_in[7];
    const float* b0     = (const float*)d_in[8];
    const float* w1     = (const float*)d_in[9];
    const float* b1     = (const float*)d_in[10];
    const float* cw     = (const float*)d_in[11];
    const float* cb     = (const float*)d_in[12];
    float* out = (float*)d_out;

    cudaFuncSetAttribute(pyramid_kernel,
                         cudaFuncAttributeMaxDynamicSharedMemorySize, SMEM_BYTES);
    pyramid_kernel<<<BATCH * 2, NTHREADS, SMEM_BYTES>>>(
        sentences, emb, comp_W, comp_b, sel_w, sel_b,
        w0, b0, w1, b1, cw, cb, out);
}